// round 1
// baseline (speedup 1.0000x reference)
#include <cuda_runtime.h>

// ---------------- problem constants ----------------
#define BQ    8
#define CCH   256
#define HFULL 160
#define WFULL 160
#define HHALF 80
#define WHALF 80
#define HWQ   6400          // 80*80
#define MTOT  51200         // 8*6400
#define K1    1024
#define N1    256
#define K2    256
#define N2    1024
#define NSEG  25            // 6400 / 256

// ---------------- scratch (device globals; no allocation allowed) --------
__device__ __align__(16) float g_W1p[K1 * N1];        // [k][o], k = c*4+q
__device__ __align__(16) float g_bias1[N1];
__device__ __align__(16) float g_W2p[K2 * N2];        // [k][j], j = c'*4+g (permuted)
__device__ __align__(16) float g_bias2p[N2];
__device__ __align__(16) float g_fused[(long)MTOT * CCH]; // 52.4 MB, [m][c]
__device__ __align__(16) float g_avg_sp[MTOT];
__device__ __align__(16) float g_max_sp[MTOT];
__device__ __align__(16) float g_gate[MTOT];
__device__ __align__(16) float g_chsum_part[NSEG * BQ * CCH];
__device__ __align__(16) float g_chmax_part[NSEG * BQ * CCH];
__device__ __align__(16) float g_chmap[BQ * CCH];

// ---------------- f32x2 helpers (Blackwell packed fp32 pipe) -------------
__device__ __forceinline__ unsigned long long pack2(float lo, float hi) {
    unsigned long long r;
    asm("mov.b64 %0, {%1, %2};" : "=l"(r) : "f"(lo), "f"(hi));
    return r;
}
__device__ __forceinline__ void unpack2(unsigned long long v, float& lo, float& hi) {
    asm("mov.b64 {%0, %1}, %2;" : "=f"(lo), "=f"(hi) : "l"(v));
}
__device__ __forceinline__ unsigned long long fma2(unsigned long long a,
                                                   unsigned long long b,
                                                   unsigned long long c) {
    unsigned long long d;
    asm("fma.rn.f32x2 %0, %1, %2, %3;" : "=l"(d) : "l"(a), "l"(b), "l"(c));
    return d;
}

// ---------------- K0a: prep fusion weights (fold DWT + BN1) --------------
// wav coefficient signs per raw-pixel q in {a,b,c,d}:
//   coeff(q) = 0.5*(w_ll + s_lh*w_lh + s_hl*w_hl + s_hh*w_hh)
__global__ void prep1(const float* __restrict__ fw, const float* __restrict__ fb,
                      const float* __restrict__ g1, const float* __restrict__ b1,
                      const float* __restrict__ m1, const float* __restrict__ v1) {
    int idx = blockIdx.x * blockDim.x + threadIdx.x;
    if (idx >= K1 * N1) return;
    int o = idx & 255;
    int k = idx >> 8;            // k = c*4 + q
    int c = k >> 2, q = k & 3;
    float inv = g1[o] * rsqrtf(v1[o] + 1e-5f);
    float slh = (q < 2) ? 1.f : -1.f;
    float shl = ((q & 1) == 0) ? 1.f : -1.f;
    float shh = slh * shl;
    float val = fw[o * 1024 + c]
              + slh * fw[o * 1024 + 256 + c]
              + shl * fw[o * 1024 + 512 + c]
              + shh * fw[o * 1024 + 768 + c];
    g_W1p[k * 256 + o] = 0.5f * inv * val;
    if (k == 0) g_bias1[o] = fb[o] * inv + b1[o] - m1[o] * inv;
}

// ---------------- K0b: prep proj weights (fold BN2, permute for iDWT) ----
__global__ void prep2(const float* __restrict__ pw, const float* __restrict__ pb,
                      const float* __restrict__ g2, const float* __restrict__ b2,
                      const float* __restrict__ m2, const float* __restrict__ v2) {
    int idx = blockIdx.x * blockDim.x + threadIdx.x;
    if (idx >= K2 * N2) return;
    int j = idx & 1023;          // j = c'*4 + g
    int k = idx >> 10;           // input channel
    int o = (j & 3) * 256 + (j >> 2);   // original projected channel
    float inv = g2[o] * rsqrtf(v2[o] + 1e-5f);
    g_W2p[k * 1024 + j] = pw[o * 256 + k] * inv;
    if (k == 0) g_bias2p[j] = pb[o] * inv + b2[o] - m2[o] * inv;
}

// ---------------- K1: GEMM1 (DWT-on-the-fly, bias+BN folded, relu) -------
// fused[m][c] = relu( sum_k A[m,k] * W1p[k][c] + bias1[c] )
// A[m, c*4+q] = x[b, c, 2h+dy, 2w+dx]
__global__ __launch_bounds__(256) void gemm1(const float* __restrict__ x) {
    __shared__ float As[16 * 128];
    __shared__ float Bs[16 * 128];
    const int tid = threadIdx.x;
    const int m0 = blockIdx.x * 128;
    const int n0 = blockIdx.y * 128;

    const int m_l = tid & 127;
    const int k_half = tid >> 7;
    const int m = m0 + m_l;
    const int bb = m / HWQ;
    const int hw = m % HWQ;
    const int h = hw / WHALF, w = hw % WHALF;
    const float* px = x + ((bb * 256) * 160 + 2 * h) * 160 + 2 * w;

    const int tm = tid >> 4, tn = tid & 15;

    unsigned long long acc[8][4];
#pragma unroll
    for (int i = 0; i < 8; i++)
#pragma unroll
        for (int p = 0; p < 4; p++) acc[i][p] = pack2(0.f, 0.f);

    for (int k0 = 0; k0 < K1; k0 += 16) {
#pragma unroll
        for (int r = 0; r < 8; r++) {
            int kl = k_half * 8 + r;
            int k = k0 + kl;
            As[kl * 128 + m_l] = px[(k >> 2) * 25600 + ((k & 2) ? 160 : 0) + (k & 1)];
            Bs[kl * 128 + m_l] = g_W1p[k * 256 + n0 + m_l];
        }
        __syncthreads();
#pragma unroll
        for (int kk = 0; kk < 16; kk++) {
            const float4 a0 = *(const float4*)(As + kk * 128 + tm * 8);
            const float4 a1 = *(const float4*)(As + kk * 128 + tm * 8 + 4);
            const float4 b0 = *(const float4*)(Bs + kk * 128 + tn * 8);
            const float4 b1 = *(const float4*)(Bs + kk * 128 + tn * 8 + 4);
            unsigned long long bp0 = pack2(b0.x, b0.y);
            unsigned long long bp1 = pack2(b0.z, b0.w);
            unsigned long long bp2 = pack2(b1.x, b1.y);
            unsigned long long bp3 = pack2(b1.z, b1.w);
            float av[8] = {a0.x, a0.y, a0.z, a0.w, a1.x, a1.y, a1.z, a1.w};
#pragma unroll
            for (int i = 0; i < 8; i++) {
                unsigned long long ad = pack2(av[i], av[i]);
                acc[i][0] = fma2(ad, bp0, acc[i][0]);
                acc[i][1] = fma2(ad, bp1, acc[i][1]);
                acc[i][2] = fma2(ad, bp2, acc[i][2]);
                acc[i][3] = fma2(ad, bp3, acc[i][3]);
            }
        }
        __syncthreads();
    }

    float bias[8];
    *(float4*)&bias[0] = *(const float4*)&g_bias1[n0 + tn * 8];
    *(float4*)&bias[4] = *(const float4*)&g_bias1[n0 + tn * 8 + 4];
#pragma unroll
    for (int i = 0; i < 8; i++) {
        float v[8];
#pragma unroll
        for (int p = 0; p < 4; p++) unpack2(acc[i][p], v[2 * p], v[2 * p + 1]);
#pragma unroll
        for (int j = 0; j < 8; j++) v[j] = fmaxf(v[j] + bias[j], 0.f);
        int mi = m0 + tm * 8 + i;
        float* dst = g_fused + (long)mi * 256 + n0 + tn * 8;
        *(float4*)dst       = make_float4(v[0], v[1], v[2], v[3]);
        *(float4*)(dst + 4) = make_float4(v[4], v[5], v[6], v[7]);
    }
}

// ---------------- K2: per-pixel channel mean/max --------------------------
__global__ void spstats() {
    int wi = threadIdx.x >> 5, lane = threadIdx.x & 31;
    int m = blockIdx.x * 8 + wi;
    const float4* f = (const float4*)(g_fused + (long)m * 256);
    float s = 0.f, mx = -1e30f;
#pragma unroll
    for (int r = 0; r < 2; r++) {
        float4 v = f[lane + r * 32];
        s += v.x + v.y + v.z + v.w;
        mx = fmaxf(mx, fmaxf(fmaxf(v.x, v.y), fmaxf(v.z, v.w)));
    }
#pragma unroll
    for (int off = 16; off; off >>= 1) {
        s += __shfl_xor_sync(0xffffffffu, s, off);
        mx = fmaxf(mx, __shfl_xor_sync(0xffffffffu, mx, off));
    }
    if (lane == 0) {
        g_avg_sp[m] = s * (1.f / 256.f);
        g_max_sp[m] = mx;
    }
}

// ---------------- K3: 7x7 spatial conv + sigmoid --------------------------
__global__ void spconv(const float* __restrict__ sa_w) {
    __shared__ float sw[98];
    if (threadIdx.x < 98) sw[threadIdx.x] = sa_w[threadIdx.x];
    __syncthreads();
    int m = blockIdx.x * 256 + threadIdx.x;
    int bb = m / HWQ, hw = m % HWQ;
    int h = hw / WHALF, w = hw % WHALF;
    float acc = 0.f;
#pragma unroll
    for (int ky = 0; ky < 7; ky++) {
        int y = h + ky - 3;
        if ((unsigned)y < 80u) {
#pragma unroll
            for (int kx = 0; kx < 7; kx++) {
                int xx = w + kx - 3;
                if ((unsigned)xx < 80u) {
                    int mi = bb * HWQ + y * WHALF + xx;
                    acc += g_avg_sp[mi] * sw[ky * 7 + kx]
                         + g_max_sp[mi] * sw[49 + ky * 7 + kx];
                }
            }
        }
    }
    g_gate[m] = 1.f / (1.f + expf(-acc));
}

// ---------------- K4: per-(b,c) sum/max of gate*fused, partials -----------
__global__ void chstats_part() {
    int bid = blockIdx.x;                 // 8*8*25 = 1600
    int bb = bid / 200;
    int rem = bid % 200;
    int cg = rem / NSEG;
    int seg = rem % NSEG;
    int cl = threadIdx.x & 31;
    int r0 = threadIdx.x >> 5;
    int c = cg * 32 + cl;
    float s = 0.f, mx = 0.f;              // values are >= 0 (relu * sigmoid)
    for (int r = r0; r < 256; r += 8) {
        int m = bb * HWQ + seg * 256 + r;
        float v = g_gate[m] * g_fused[(long)m * 256 + c];
        s += v;
        mx = fmaxf(mx, v);
    }
    __shared__ float ss[256], sm_[256];
    ss[threadIdx.x] = s;
    sm_[threadIdx.x] = mx;
    __syncthreads();
    if (r0 == 0) {
#pragma unroll
        for (int r = 1; r < 8; r++) {
            s += ss[r * 32 + cl];
            mx = fmaxf(mx, sm_[r * 32 + cl]);
        }
        g_chsum_part[(seg * BQ + bb) * 256 + c] = s;
        g_chmax_part[(seg * BQ + bb) * 256 + c] = mx;
    }
}

// ---------------- K5: finalize stats + channel MLP + sigmoid --------------
__global__ void chmlp(const float* __restrict__ w1, const float* __restrict__ w2) {
    int bb = blockIdx.x;
    int tid = threadIdx.x;
    __shared__ float sA[256], sM[256], sH[32];
    float s = 0.f, mx = 0.f;
    for (int seg = 0; seg < NSEG; seg++) {
        s += g_chsum_part[(seg * BQ + bb) * 256 + tid];
        mx = fmaxf(mx, g_chmax_part[(seg * BQ + bb) * 256 + tid]);
    }
    sA[tid] = s * (1.f / 6400.f);
    sM[tid] = mx;
    __syncthreads();
    int warp = tid >> 5, lane = tid & 31;
#pragma unroll
    for (int it = 0; it < 4; it++) {
        int t = warp * 4 + it;            // 0..31
        int u = t & 15, which = t >> 4;
        const float* vec = which ? sM : sA;
        float d = 0.f;
        for (int cc = lane; cc < 256; cc += 32) d += w1[u * 256 + cc] * vec[cc];
#pragma unroll
        for (int off = 16; off; off >>= 1) d += __shfl_xor_sync(0xffffffffu, d, off);
        if (lane == 0) sH[t] = fmaxf(d, 0.f);
    }
    __syncthreads();
    float o = 0.f;
#pragma unroll
    for (int u = 0; u < 16; u++) o += w2[tid * 16 + u] * (sH[u] + sH[16 + u]);
    g_chmap[bb * 256 + tid] = 1.f / (1.f + expf(-o));
}

// ---------------- K6: GEMM2 with fused ch/sp gating + iDWT + identity -----
__global__ __launch_bounds__(256) void gemm2(const float* __restrict__ x,
                                             float* __restrict__ out) {
    __shared__ float As[128 * 17];        // [m][k], padded
    __shared__ float Bs[16 * 128];        // [k][j]
    __shared__ float S[16 * 128];         // epilogue staging [j_l][m]
    __shared__ float gate_s[128];
    __shared__ float cmap_s[256];
    const int tid = threadIdx.x;
    const int m0 = blockIdx.x * 128;
    const int n0 = blockIdx.y * 128;
    const int bb = m0 / HWQ;

    if (tid < 128) gate_s[tid] = g_gate[m0 + tid];
    cmap_s[tid] = g_chmap[bb * 256 + tid];
    __syncthreads();

    const int tm = tid >> 4, tn = tid & 15;

    unsigned long long acc[8][4];
#pragma unroll
    for (int i = 0; i < 8; i++)
#pragma unroll
        for (int p = 0; p < 4; p++) acc[i][p] = pack2(0.f, 0.f);

    for (int k0 = 0; k0 < K2; k0 += 16) {
#pragma unroll
        for (int r = 0; r < 8; r++) {
            int e = tid + r * 256;
            int ml = e >> 4, kl = e & 15;
            As[ml * 17 + kl] =
                g_fused[(long)(m0 + ml) * 256 + k0 + kl] * gate_s[ml] * cmap_s[k0 + kl];
            int nl = e & 127, kl2 = e >> 7;
            Bs[kl2 * 128 + nl] = g_W2p[(k0 + kl2) * 1024 + n0 + nl];
        }
        __syncthreads();
#pragma unroll
        for (int kk = 0; kk < 16; kk++) {
            const float4 b0 = *(const float4*)(Bs + kk * 128 + tn * 8);
            const float4 b1 = *(const float4*)(Bs + kk * 128 + tn * 8 + 4);
            unsigned long long bp0 = pack2(b0.x, b0.y);
            unsigned long long bp1 = pack2(b0.z, b0.w);
            unsigned long long bp2 = pack2(b1.x, b1.y);
            unsigned long long bp3 = pack2(b1.z, b1.w);
#pragma unroll
            for (int i = 0; i < 8; i++) {
                float a = As[(tm * 8 + i) * 17 + kk];
                unsigned long long ad = pack2(a, a);
                acc[i][0] = fma2(ad, bp0, acc[i][0]);
                acc[i][1] = fma2(ad, bp1, acc[i][1]);
                acc[i][2] = fma2(ad, bp2, acc[i][2]);
                acc[i][3] = fma2(ad, bp3, acc[i][3]);
            }
        }
        __syncthreads();
    }

    // bias (permuted order) for this thread's 8 columns
    float bias[8];
    *(float4*)&bias[0] = *(const float4*)&g_bias2p[n0 + tn * 8];
    *(float4*)&bias[4] = *(const float4*)&g_bias2p[n0 + tn * 8 + 4];

    // Epilogue in 8 chunks of 16 j-columns: bias+relu -> stage -> iDWT -> out
    const int myg = tn >> 1;
    const int jhalf = tn & 1;
    for (int g = 0; g < 8; g++) {
        if (myg == g) {
#pragma unroll
            for (int i = 0; i < 8; i++) {
                float v[8];
#pragma unroll
                for (int p = 0; p < 4; p++) unpack2(acc[i][p], v[2 * p], v[2 * p + 1]);
#pragma unroll
                for (int j = 0; j < 8; j++) {
                    float val = fmaxf(v[j] + bias[j], 0.f);
                    S[(jhalf * 8 + j) * 128 + tm * 8 + i] = val;
                }
            }
        }
        __syncthreads();
        // chunk holds 4 c' channels x 128 pixels, all 4 wavelet comps each
#pragma unroll
        for (int pp = 0; pp < 2; pp++) {
            int p = tid + pp * 256;          // 0..511
            int m_l = p & 127;
            int cl = p >> 7;                 // 0..3
            float ll = S[(cl * 4 + 0) * 128 + m_l];
            float lh = S[(cl * 4 + 1) * 128 + m_l];
            float hl = S[(cl * 4 + 2) * 128 + m_l];
            float hh = S[(cl * 4 + 3) * 128 + m_l];
            float oa = 0.5f * (ll + lh + hl + hh);
            float ob = 0.5f * (ll + lh - hl - hh);
            float oc = 0.5f * (ll - lh + hl - hh);
            float od = 0.5f * (ll - lh - hl + hh);
            int m = m0 + m_l;
            int hw = m % HWQ;
            int h = hw / WHALF, w = hw % WHALF;
            int cp = ((n0 + g * 16) >> 2) + cl;
            long base = (((long)bb * 256 + cp) * 160 + 2 * h) * 160 + 2 * w;
            float2 x01 = *(const float2*)(x + base);
            float2 x23 = *(const float2*)(x + base + 160);
            *(float2*)(out + base)       = make_float2(oa + x01.x, ob + x01.y);
            *(float2*)(out + base + 160) = make_float2(oc + x23.x, od + x23.y);
        }
        __syncthreads();
    }
}

// ---------------- host launch ---------------------------------------------
extern "C" void kernel_launch(void* const* d_in, const int* in_sizes, int n_in,
                              void* d_out, int out_size) {
    (void)in_sizes; (void)n_in; (void)out_size;
    const float* x        = (const float*)d_in[0];
    const float* fusion_w = (const float*)d_in[1];
    const float* fusion_b = (const float*)d_in[2];
    const float* bn1_g    = (const float*)d_in[3];
    const float* bn1_b    = (const float*)d_in[4];
    const float* bn1_m    = (const float*)d_in[5];
    const float* bn1_v    = (const float*)d_in[6];
    const float* sa_w     = (const float*)d_in[7];
    const float* ca_w1    = (const float*)d_in[8];
    const float* ca_w2    = (const float*)d_in[9];
    const float* proj_w   = (const float*)d_in[10];
    const float* proj_b   = (const float*)d_in[11];
    const float* bn2_g    = (const float*)d_in[12];
    const float* bn2_b    = (const float*)d_in[13];
    const float* bn2_m    = (const float*)d_in[14];
    const float* bn2_v    = (const float*)d_in[15];
    float* out = (float*)d_out;

    prep1<<<(K1 * N1) / 256, 256>>>(fusion_w, fusion_b, bn1_g, bn1_b, bn1_m, bn1_v);
    prep2<<<(K2 * N2) / 256, 256>>>(proj_w, proj_b, bn2_g, bn2_b, bn2_m, bn2_v);
    gemm1<<<dim3(MTOT / 128, N1 / 128), 256>>>(x);
    spstats<<<MTOT / 8, 256>>>();
    spconv<<<MTOT / 256, 256>>>(sa_w);
    chstats_part<<<BQ * 8 * NSEG, 256>>>();
    chmlp<<<BQ, 256>>>(ca_w1, ca_w2);
    gemm2<<<dim3(MTOT / 128, N2 / 128), 256>>>(x, out);
}